// round 1
// baseline (speedup 1.0000x reference)
#include <cuda_runtime.h>

// Problem constants (fixed by the reference)
#define IN_F   4096
#define OUT_F  11008
#define GROUPS_PER_ROW (IN_F / 16)   // 256 groups along K per output row

// Tiling
#define BM 128
#define BN 128
#define BK 16
#define NTHREADS 256

__global__ __launch_bounds__(NTHREADS, 2)
void linear3bit_sgemm(const float* __restrict__ X,     // [M, IN_F]
                      const int*   __restrict__ Q,     // [NUM_GROUPS, 8] int32, 2x3bit per int
                      const float* __restrict__ NORM,  // [NUM_GROUPS]
                      const float* __restrict__ BIAS,  // [OUT_F]
                      float*       __restrict__ C,     // [M, OUT_F]
                      int M)
{
    __shared__ __align__(16) float As[BK][BM];   // As[k][m]
    __shared__ __align__(16) float Bs[BK][BN];   // Bs[k][n]

    const int tid = threadIdx.x;
    const int bn  = blockIdx.x;   // N tile index (0..85)
    const int bm  = blockIdx.y;   // M tile index

    // ---- A-tile loading map: thread -> (row, 8 consecutive k) ----
    const int arow = tid >> 1;                 // 0..127
    const int acol = (tid & 1) * 8;            // 0 or 8
    const float* Aptr = X + (size_t)(bm * BM + arow) * IN_F + acol;

    // ---- B-tile loading map: thread -> (n row, half of one quant group) ----
    const int brow = tid >> 1;                 // n within tile, 0..127
    const int bj   = (tid & 1) * 4;            // int32 offset within the group's 8 ints
    const long long gbase = (long long)(bn * BN + brow) * GROUPS_PER_ROW;

    // ---- compute map: 16x16 thread grid, 4+4 split rows/cols ----
    const int tx = tid & 15;
    const int ty = tid >> 4;

    float acc[8][8];
#pragma unroll
    for (int i = 0; i < 8; i++)
#pragma unroll
        for (int j = 0; j < 8; j++) acc[i][j] = 0.0f;

    // ---- register prefetch of tile kt=0 ----
    float4 pa0 = *reinterpret_cast<const float4*>(Aptr);
    float4 pa1 = *reinterpret_cast<const float4*>(Aptr + 4);
    int4   pq  = *reinterpret_cast<const int4*>(Q + gbase * 8 + bj);
    float  pn  = __ldg(NORM + gbase);

    const int NKT = IN_F / BK;   // 256
    for (int kt = 0; kt < NKT; kt++) {
        // ---- stage prefetched tile into shared ----
        As[acol + 0][arow] = pa0.x;
        As[acol + 1][arow] = pa0.y;
        As[acol + 2][arow] = pa0.z;
        As[acol + 3][arow] = pa0.w;
        As[acol + 4][arow] = pa1.x;
        As[acol + 5][arow] = pa1.y;
        As[acol + 6][arow] = pa1.z;
        As[acol + 7][arow] = pa1.w;

        {
            const float s  = pn * (2.0f / 7.0f);
            const int   kb = bj * 2;
            Bs[kb + 0][brow] = (float)( pq.x        & 7) * s - pn;
            Bs[kb + 1][brow] = (float)((pq.x >> 3)  & 7) * s - pn;
            Bs[kb + 2][brow] = (float)( pq.y        & 7) * s - pn;
            Bs[kb + 3][brow] = (float)((pq.y >> 3)  & 7) * s - pn;
            Bs[kb + 4][brow] = (float)( pq.z        & 7) * s - pn;
            Bs[kb + 5][brow] = (float)((pq.z >> 3)  & 7) * s - pn;
            Bs[kb + 6][brow] = (float)( pq.w        & 7) * s - pn;
            Bs[kb + 7][brow] = (float)((pq.w >> 3)  & 7) * s - pn;
        }
        __syncthreads();

        // ---- prefetch next tile (overlaps with compute below) ----
        if (kt + 1 < NKT) {
            const float* ap = Aptr + (kt + 1) * BK;
            pa0 = *reinterpret_cast<const float4*>(ap);
            pa1 = *reinterpret_cast<const float4*>(ap + 4);
            const long long g = gbase + (kt + 1);
            pq = *reinterpret_cast<const int4*>(Q + g * 8 + bj);
            pn = __ldg(NORM + g);
        }

        // ---- compute 16 k-steps on the staged tile ----
#pragma unroll
        for (int kk = 0; kk < BK; kk++) {
            float a[8], b[8];
            float4 av0 = *reinterpret_cast<const float4*>(&As[kk][ty * 4]);
            float4 av1 = *reinterpret_cast<const float4*>(&As[kk][ty * 4 + 64]);
            float4 bv0 = *reinterpret_cast<const float4*>(&Bs[kk][tx * 4]);
            float4 bv1 = *reinterpret_cast<const float4*>(&Bs[kk][tx * 4 + 64]);
            a[0] = av0.x; a[1] = av0.y; a[2] = av0.z; a[3] = av0.w;
            a[4] = av1.x; a[5] = av1.y; a[6] = av1.z; a[7] = av1.w;
            b[0] = bv0.x; b[1] = bv0.y; b[2] = bv0.z; b[3] = bv0.w;
            b[4] = bv1.x; b[5] = bv1.y; b[6] = bv1.z; b[7] = bv1.w;
#pragma unroll
            for (int i = 0; i < 8; i++)
#pragma unroll
                for (int j = 0; j < 8; j++)
                    acc[i][j] = fmaf(a[i], b[j], acc[i][j]);
        }
        __syncthreads();
    }

    // ---- epilogue: add bias, write 2x (4 rows x 2 float4) blocks ----
    const int ncol0 = bn * BN + tx * 4;        // cols for j=0..3
    const int ncol1 = ncol0 + 64;              // cols for j=4..7
    float4 bias0, bias1;
    bias0.x = BIAS[ncol0 + 0]; bias0.y = BIAS[ncol0 + 1];
    bias0.z = BIAS[ncol0 + 2]; bias0.w = BIAS[ncol0 + 3];
    bias1.x = BIAS[ncol1 + 0]; bias1.y = BIAS[ncol1 + 1];
    bias1.z = BIAS[ncol1 + 2]; bias1.w = BIAS[ncol1 + 3];

#pragma unroll
    for (int i = 0; i < 8; i++) {
        const int mrow = bm * BM + ((i < 4) ? (ty * 4 + i) : (64 + ty * 4 + (i - 4)));
        float* crow = C + (size_t)mrow * OUT_F;
        float4 o0, o1;
        o0.x = acc[i][0] + bias0.x; o0.y = acc[i][1] + bias0.y;
        o0.z = acc[i][2] + bias0.z; o0.w = acc[i][3] + bias0.w;
        o1.x = acc[i][4] + bias1.x; o1.y = acc[i][5] + bias1.y;
        o1.z = acc[i][6] + bias1.z; o1.w = acc[i][7] + bias1.w;
        *reinterpret_cast<float4*>(crow + ncol0) = o0;
        *reinterpret_cast<float4*>(crow + ncol1) = o1;
    }
}

extern "C" void kernel_launch(void* const* d_in, const int* in_sizes, int n_in,
                              void* d_out, int out_size)
{
    const float* x    = (const float*)d_in[0];   // [4,2048,4096] fp32
    const int*   q3   = (const int*)  d_in[1];   // [2818048, 8] int32
    const float* nrm  = (const float*)d_in[2];   // [2818048, 1] fp32
    const float* bias = (const float*)d_in[3];   // [11008] fp32
    float* out = (float*)d_out;                  // [4,2048,11008] fp32

    const int M = in_sizes[0] / IN_F;            // 8192
    dim3 grid(OUT_F / BN, M / BM);               // (86, 64)
    linear3bit_sgemm<<<grid, NTHREADS>>>(x, q3, nrm, bias, out, M);
}

// round 3
// speedup vs baseline: 3.1320x; 3.1320x over previous
#include <cuda_runtime.h>
#include <cstdint>

#define IN_F   4096
#define OUT_F  11008
#define M_MAX  8192
#define NGROUPS (OUT_F * (IN_F / 16))   // 2818048

// ---------------- scratch (static device arrays) ----------------
__device__ __align__(1024) float g_w[(size_t)OUT_F * IN_F];   // dequantized W (tf32-rounded)
__device__ __align__(1024) float g_x[(size_t)M_MAX * IN_F];   // X (tf32-rounded)

__device__ __forceinline__ float tf32r(float x) {
    uint32_t u;
    asm("cvt.rna.tf32.f32 %0, %1;" : "=r"(u) : "f"(x));
    return __uint_as_float(u);
}

// ---------------- kernel 1: dequant W -> fp32 (tf32-rounded) ----------------
__global__ void dequant_w_kernel(const int* __restrict__ Q, const float* __restrict__ NORM) {
    size_t g = (size_t)blockIdx.x * 256 + threadIdx.x;  // exactly NGROUPS threads
    const int4* qp = reinterpret_cast<const int4*>(Q + g * 8);
    int4 q0 = qp[0];
    int4 q1 = qp[1];
    float n = NORM[g];
    float s = n * (2.0f / 7.0f);
    int v[8] = {q0.x, q0.y, q0.z, q0.w, q1.x, q1.y, q1.z, q1.w};
    float w[16];
#pragma unroll
    for (int i = 0; i < 8; i++) {
        w[2 * i + 0] = tf32r(fmaf((float)(v[i] & 7), s, -n));
        w[2 * i + 1] = tf32r(fmaf((float)((v[i] >> 3) & 7), s, -n));
    }
    float4* dst = reinterpret_cast<float4*>(g_w + g * 16);
#pragma unroll
    for (int i = 0; i < 4; i++) {
        float4 o;
        o.x = w[4 * i + 0]; o.y = w[4 * i + 1]; o.z = w[4 * i + 2]; o.w = w[4 * i + 3];
        dst[i] = o;
    }
}

// ---------------- kernel 2: round X -> tf32 ----------------
__global__ void round_x_kernel(const float4* __restrict__ X) {
    size_t i = (size_t)blockIdx.x * 256 + threadIdx.x;
    float4 v = X[i];
    v.x = tf32r(v.x); v.y = tf32r(v.y); v.z = tf32r(v.z); v.w = tf32r(v.w);
    reinterpret_cast<float4*>(g_x)[i] = v;
}

// ---------------- kernel 3: pipelined mma.sync tf32 GEMM ----------------
#define BM 128
#define BN 128
#define BK 32
#define STAGES 4
#define STAGE_FLOATS (BM * BK + BN * BK)             // 8192 floats = 32 KB
#define SMEM_BYTES (STAGES * STAGE_FLOATS * 4)       // 128 KB
#define NKT (IN_F / BK)                               // 128

__device__ __forceinline__ void cp16(uint32_t dst, const void* src) {
    asm volatile("cp.async.cg.shared.global [%0], [%1], 16;" :: "r"(dst), "l"(src));
}

__device__ __forceinline__ void mma_tf32(float* d, const uint32_t* a, const uint32_t* b) {
    asm volatile(
        "mma.sync.aligned.m16n8k8.row.col.f32.tf32.tf32.f32 "
        "{%0,%1,%2,%3}, {%4,%5,%6,%7}, {%8,%9}, {%0,%1,%2,%3};"
        : "+f"(d[0]), "+f"(d[1]), "+f"(d[2]), "+f"(d[3])
        : "r"(a[0]), "r"(a[1]), "r"(a[2]), "r"(a[3]),
          "r"(b[0]), "r"(b[1]));
}

__global__ __launch_bounds__(256, 1)
void gemm_mma_tf32(const float* __restrict__ A,     // g_x [M, K]
                   const float* __restrict__ B,     // g_w [N, K]
                   const float* __restrict__ bias,
                   float* __restrict__ C,
                   int mtiles)
{
    extern __shared__ __align__(1024) float smem[];
    const int tid  = threadIdx.x;
    const int lane = tid & 31;
    const int warp = tid >> 5;
    const int wm   = warp & 1;          // 0..1  (M dir, 64 rows each)
    const int wn   = warp >> 1;         // 0..3  (N dir, 32 cols each)
    const int g    = lane >> 2;         // 0..7
    const int tig  = lane & 3;          // 0..3

    // ---- grouped rasterization (GM m-tiles per group, n fastest->slowest mix) ----
    const int NT = OUT_F / BN;          // 86
    const int GM = 8;
    int bid   = blockIdx.x;
    int grp   = bid / (GM * NT);
    int first = grp * GM;
    int gsz   = (mtiles - first < GM) ? (mtiles - first) : GM;
    int rem   = bid - grp * GM * NT;
    int mt    = first + rem % gsz;
    int nt    = rem / gsz;
    const int m0 = mt * BM;
    const int n0 = nt * BN;

    const float* gA = A + (size_t)m0 * IN_F;
    const float* gB = B + (size_t)n0 * IN_F;

    // ---- cp.async tile loader: 128 rows x 8 chunks(16B) each for A and B ----
    // chunk c: row = c>>3, kc = c&7 ; swizzled dst col = kc*4 ^ ((row&7)<<2)
    const int lrow = tid >> 3;          // base row for i-strided loads (+32 per i)
    const int lkc  = tid & 7;
    const uint32_t s_a_base = (uint32_t)__cvta_generic_to_shared(smem);

    float acc[4][4][4];
#pragma unroll
    for (int mi = 0; mi < 4; mi++)
#pragma unroll
        for (int ni = 0; ni < 4; ni++)
#pragma unroll
            for (int q = 0; q < 4; q++) acc[mi][ni][q] = 0.0f;

#define LOAD_TILE(stg, kt) do {                                                   \
    uint32_t sa = s_a_base + (uint32_t)((stg) * STAGE_FLOATS) * 4;                \
    uint32_t sb = sa + BM * BK * 4;                                               \
    _Pragma("unroll")                                                             \
    for (int i = 0; i < 4; i++) {                                                 \
        int row = lrow + i * 32;                                                  \
        uint32_t dcol = (uint32_t)((lkc * 4) ^ ((row & 7) << 2));                 \
        cp16(sa + (uint32_t)(row * BK + dcol) * 4,                                \
             gA + (size_t)row * IN_F + (kt) * BK + lkc * 4);                      \
        cp16(sb + (uint32_t)(row * BK + dcol) * 4,                                \
             gB + (size_t)row * IN_F + (kt) * BK + lkc * 4);                      \
    }                                                                             \
    asm volatile("cp.async.commit_group;");                                       \
} while (0)

    // ---- prologue: stages 0..STAGES-2 ----
#pragma unroll
    for (int s = 0; s < STAGES - 1; s++) LOAD_TILE(s, s);

    for (int t = 0; t < NKT; t++) {
        asm volatile("cp.async.wait_group %0;" :: "n"(STAGES - 2));
        __syncthreads();

        int nxt = t + STAGES - 1;
        if (nxt < NKT) {
            LOAD_TILE(nxt % STAGES, nxt);
        } else {
            asm volatile("cp.async.commit_group;");
        }

        // ---- compute on stage t%STAGES ----
        const float* sA = smem + (t % STAGES) * STAGE_FLOATS;
        const float* sB = sA + BM * BK;
#pragma unroll
        for (int ks = 0; ks < 4; ks++) {
            const int k0  = ks * 8;
            const int ca0 = (k0 + tig) ^ (g << 2);
            const int ca1 = ca0 ^ 4;

            uint32_t a[4][4], b[4][2];
#pragma unroll
            for (int mi = 0; mi < 4; mi++) {
                const float* ar = sA + (wm * 64 + mi * 16 + g) * BK;
                a[mi][0] = __float_as_uint(ar[ca0]);
                a[mi][1] = __float_as_uint(ar[8 * BK + ca0]);
                a[mi][2] = __float_as_uint(ar[ca1]);
                a[mi][3] = __float_as_uint(ar[8 * BK + ca1]);
            }
#pragma unroll
            for (int ni = 0; ni < 4; ni++) {
                const float* br = sB + (wn * 32 + ni * 8 + g) * BK;
                b[ni][0] = __float_as_uint(br[ca0]);
                b[ni][1] = __float_as_uint(br[ca1]);
            }
#pragma unroll
            for (int mi = 0; mi < 4; mi++)
#pragma unroll
                for (int ni = 0; ni < 4; ni++)
                    mma_tf32(acc[mi][ni], a[mi], b[ni]);
        }
        __syncthreads();
    }

    // ---- epilogue: bias + store ----
#pragma unroll
    for (int mi = 0; mi < 4; mi++) {
        const int row = m0 + wm * 64 + mi * 16 + g;
        float* c0 = C + (size_t)row * OUT_F;
        float* c1 = C + (size_t)(row + 8) * OUT_F;
#pragma unroll
        for (int ni = 0; ni < 4; ni++) {
            const int col = n0 + wn * 32 + ni * 8 + tig * 2;
            float2 bv = *reinterpret_cast<const float2*>(bias + col);
            float2 o0, o1;
            o0.x = acc[mi][ni][0] + bv.x;
            o0.y = acc[mi][ni][1] + bv.y;
            o1.x = acc[mi][ni][2] + bv.x;
            o1.y = acc[mi][ni][3] + bv.y;
            *reinterpret_cast<float2*>(c0 + col) = o0;
            *reinterpret_cast<float2*>(c1 + col) = o1;
        }
    }
}

// ---------------- host launcher ----------------
extern "C" void kernel_launch(void* const* d_in, const int* in_sizes, int n_in,
                              void* d_out, int out_size)
{
    const float* x    = (const float*)d_in[0];
    const int*   q3   = (const int*)  d_in[1];
    const float* nrm  = (const float*)d_in[2];
    const float* bias = (const float*)d_in[3];
    float* out = (float*)d_out;

    const int M = in_sizes[0] / IN_F;            // 8192

    void* wptr = nullptr; cudaGetSymbolAddress(&wptr, g_w);
    void* xptr = nullptr; cudaGetSymbolAddress(&xptr, g_x);

    dequant_w_kernel<<<NGROUPS / 256, 256>>>(q3, nrm);
    round_x_kernel<<<(int)(((size_t)M * IN_F / 4) / 256), 256>>>(
        reinterpret_cast<const float4*>(x));

    cudaFuncSetAttribute(gemm_mma_tf32,
                         cudaFuncAttributeMaxDynamicSharedMemorySize, SMEM_BYTES);
    const int mtiles = M / BM;                   // 64
    const int grid = mtiles * (OUT_F / BN);      // 64 * 86 = 5504
    gemm_mma_tf32<<<grid, 256, SMEM_BYTES>>>((const float*)xptr, (const float*)wptr,
                                             bias, out, mtiles);
}

// round 5
// speedup vs baseline: 6.0639x; 1.9361x over previous
#include <cuda_runtime.h>
#include <cuda_fp16.h>
#include <cstdint>

#define IN_F   4096
#define OUT_F  11008
#define M_MAX  8192
#define NGROUPS (OUT_F * (IN_F / 16))   // 2818048

// ---------------- scratch (static device arrays) ----------------
__device__ __align__(1024) __half g_wh[(size_t)OUT_F * IN_F];  // dequantized W, fp16
__device__ __align__(1024) __half g_xh[(size_t)M_MAX * IN_F];  // X, fp16

__device__ __forceinline__ uint32_t h2u(__half2 h) {
    union { __half2 h; uint32_t u; } c;
    c.h = h;
    return c.u;
}

// ---------------- kernel 1: dequant W -> fp16 ----------------
__global__ void dequant_w_kernel(const int* __restrict__ Q, const float* __restrict__ NORM) {
    size_t g = (size_t)blockIdx.x * 256 + threadIdx.x;  // exactly NGROUPS threads
    const int4* qp = reinterpret_cast<const int4*>(Q + g * 8);
    int4 q0 = qp[0];
    int4 q1 = qp[1];
    float n = NORM[g];
    float s = n * (2.0f / 7.0f);
    int v[8] = {q0.x, q0.y, q0.z, q0.w, q1.x, q1.y, q1.z, q1.w};
    uint32_t h[8];
#pragma unroll
    for (int i = 0; i < 8; i++) {
        float w0 = fmaf((float)(v[i] & 7), s, -n);
        float w1 = fmaf((float)((v[i] >> 3) & 7), s, -n);
        h[i] = h2u(__floats2half2_rn(w0, w1));
    }
    uint4* dst = reinterpret_cast<uint4*>(g_wh + g * 16);
    uint4 o0, o1;
    o0.x = h[0]; o0.y = h[1]; o0.z = h[2]; o0.w = h[3];
    o1.x = h[4]; o1.y = h[5]; o1.z = h[6]; o1.w = h[7];
    dst[0] = o0;
    dst[1] = o1;
}

// ---------------- kernel 2: X -> fp16 ----------------
__global__ void conv_x_kernel(const float4* __restrict__ X) {
    size_t i = (size_t)blockIdx.x * 256 + threadIdx.x;   // each handles 8 floats
    float4 v0 = X[2 * i];
    float4 v1 = X[2 * i + 1];
    uint4 o;
    o.x = h2u(__floats2half2_rn(v0.x, v0.y));
    o.y = h2u(__floats2half2_rn(v0.z, v0.w));
    o.z = h2u(__floats2half2_rn(v1.x, v1.y));
    o.w = h2u(__floats2half2_rn(v1.z, v1.w));
    reinterpret_cast<uint4*>(g_xh)[i] = o;
}

// ---------------- kernel 3: pipelined fp16 mma GEMM ----------------
// BM=128, BN=128, BK=64 halves. Row = 128 B = 32 words. Same swizzle/addressing
// geometry as the (verified) round-3 fp32/BK=32 kernel.
#define BM 128
#define BN 128
#define BKH 64                                   // K per tile, in halves
#define ROWW 32                                  // words per smem row
#define STAGES 4
#define STAGE_WORDS (BM * ROWW + BN * ROWW)      // 8192 words = 32 KB
#define SMEM_BYTES (STAGES * STAGE_WORDS * 4)    // 128 KB
#define NKT (IN_F / BKH)                          // 64

__device__ __forceinline__ void cp16(uint32_t dst, const void* src) {
    asm volatile("cp.async.cg.shared.global [%0], [%1], 16;" :: "r"(dst), "l"(src));
}

__device__ __forceinline__ void mma_f16(float* d, const uint32_t* a, const uint32_t* b) {
    asm volatile(
        "mma.sync.aligned.m16n8k16.row.col.f32.f16.f16.f32 "
        "{%0,%1,%2,%3}, {%4,%5,%6,%7}, {%8,%9}, {%0,%1,%2,%3};"
        : "+f"(d[0]), "+f"(d[1]), "+f"(d[2]), "+f"(d[3])
        : "r"(a[0]), "r"(a[1]), "r"(a[2]), "r"(a[3]),
          "r"(b[0]), "r"(b[1]));
}

__global__ __launch_bounds__(256, 1)
void gemm_mma_f16(const __half* __restrict__ A,     // g_xh [M, K]
                  const __half* __restrict__ B,     // g_wh [N, K]
                  const float* __restrict__ bias,
                  float* __restrict__ C,
                  int mtiles)
{
    extern __shared__ __align__(1024) uint32_t smw[];
    const int tid  = threadIdx.x;
    const int lane = tid & 31;
    const int warp = tid >> 5;
    const int wm   = warp & 1;          // M dir (64 rows each)
    const int wn   = warp >> 1;         // N dir (32 cols each)
    const int g    = lane >> 2;         // 0..7
    const int tig  = lane & 3;          // 0..3

    // ---- grouped rasterization ----
    const int NT = OUT_F / BN;          // 86
    const int GM = 8;
    int bid   = blockIdx.x;
    int grp   = bid / (GM * NT);
    int first = grp * GM;
    int gsz   = (mtiles - first < GM) ? (mtiles - first) : GM;
    int rem   = bid - grp * GM * NT;
    int mt    = first + rem % gsz;
    int nt    = rem / gsz;
    const int m0 = mt * BM;
    const int n0 = nt * BN;

    const __half* gA = A + (size_t)m0 * IN_F;
    const __half* gB = B + (size_t)n0 * IN_F;

    // loader map: row = lrow + 32*i, 16B chunk lkc (8 chunks/row)
    const int lrow = tid >> 3;
    const int lkc  = tid & 7;
    const uint32_t s_base = (uint32_t)__cvta_generic_to_shared(smw);

    float acc[4][4][4];
#pragma unroll
    for (int mi = 0; mi < 4; mi++)
#pragma unroll
        for (int ni = 0; ni < 4; ni++)
#pragma unroll
            for (int q = 0; q < 4; q++) acc[mi][ni][q] = 0.0f;

#define LOAD_TILE(stg, kt) do {                                                   \
    uint32_t sa = s_base + (uint32_t)((stg) * STAGE_WORDS) * 4;                   \
    uint32_t sb = sa + BM * ROWW * 4;                                             \
    _Pragma("unroll")                                                             \
    for (int i = 0; i < 4; i++) {                                                 \
        int row = lrow + i * 32;                                                  \
        uint32_t schunk = (uint32_t)(lkc ^ (row & 7));                            \
        cp16(sa + (uint32_t)(row * ROWW + schunk * 4) * 4,                        \
             gA + (size_t)row * IN_F + (kt) * BKH + lkc * 8);                     \
        cp16(sb + (uint32_t)(row * ROWW + schunk * 4) * 4,                        \
             gB + (size_t)row * IN_F + (kt) * BKH + lkc * 8);                     \
    }                                                                             \
    asm volatile("cp.async.commit_group;");                                       \
} while (0)

#pragma unroll
    for (int s = 0; s < STAGES - 1; s++) LOAD_TILE(s, s);

    for (int t = 0; t < NKT; t++) {
        asm volatile("cp.async.wait_group %0;" :: "n"(STAGES - 2));
        __syncthreads();

        int nxt = t + STAGES - 1;
        if (nxt < NKT) {
            LOAD_TILE(nxt % STAGES, nxt);
        } else {
            asm volatile("cp.async.commit_group;");
        }

        const uint32_t* sA = smw + (t % STAGES) * STAGE_WORDS;
        const uint32_t* sB = sA + BM * ROWW;
#pragma unroll
        for (int ks = 0; ks < 4; ks++) {
            const int k0w = ks * 8;                       // word base within row
            const int ca0 = (k0w + tig) ^ (g << 2);
            const int ca1 = ca0 ^ 4;

            uint32_t a[4][4], b[4][2];
#pragma unroll
            for (int mi = 0; mi < 4; mi++) {
                const uint32_t* ar = sA + (wm * 64 + mi * 16 + g) * ROWW;
                a[mi][0] = ar[ca0];
                a[mi][1] = ar[8 * ROWW + ca0];
                a[mi][2] = ar[ca1];
                a[mi][3] = ar[8 * ROWW + ca1];
            }
#pragma unroll
            for (int ni = 0; ni < 4; ni++) {
                const uint32_t* br = sB + (wn * 32 + ni * 8 + g) * ROWW;
                b[ni][0] = br[ca0];
                b[ni][1] = br[ca1];
            }
#pragma unroll
            for (int mi = 0; mi < 4; mi++)
#pragma unroll
                for (int ni = 0; ni < 4; ni++)
                    mma_f16(acc[mi][ni], a[mi], b[ni]);
        }
        __syncthreads();
    }

    // ---- epilogue: bias + store ----
#pragma unroll
    for (int mi = 0; mi < 4; mi++) {
        const int row = m0 + wm * 64 + mi * 16 + g;
        float* c0 = C + (size_t)row * OUT_F;
        float* c1 = C + (size_t)(row + 8) * OUT_F;
#pragma unroll
        for (int ni = 0; ni < 4; ni++) {
            const int col = n0 + wn * 32 + ni * 8 + tig * 2;
            float2 bv = *reinterpret_cast<const float2*>(bias + col);
            float2 o0, o1;
            o0.x = acc[mi][ni][0] + bv.x;
            o0.y = acc[mi][ni][1] + bv.y;
            o1.x = acc[mi][ni][2] + bv.x;
            o1.y = acc[mi][ni][3] + bv.y;
            *reinterpret_cast<float2*>(c0 + col) = o0;
            *reinterpret_cast<float2*>(c1 + col) = o1;
        }
    }
}

// ---------------- host launcher ----------------
extern "C" void kernel_launch(void* const* d_in, const int* in_sizes, int n_in,
                              void* d_out, int out_size)
{
    const float* x    = (const float*)d_in[0];
    const int*   q3   = (const int*)  d_in[1];
    const float* nrm  = (const float*)d_in[2];
    const float* bias = (const float*)d_in[3];
    float* out = (float*)d_out;

    const int M = in_sizes[0] / IN_F;            // 8192

    void* wptr = nullptr; cudaGetSymbolAddress(&wptr, g_wh);
    void* xptr = nullptr; cudaGetSymbolAddress(&xptr, g_xh);

    dequant_w_kernel<<<NGROUPS / 256, 256>>>(q3, nrm);
    conv_x_kernel<<<(int)(((size_t)M * IN_F / 8) / 256), 256>>>(
        reinterpret_cast<const float4*>(x));

    cudaFuncSetAttribute(gemm_mma_f16,
                         cudaFuncAttributeMaxDynamicSharedMemorySize, SMEM_BYTES);
    const int mtiles = M / BM;                   // 64
    const int grid = mtiles * (OUT_F / BN);      // 5504
    gemm_mma_f16<<<grid, 256, SMEM_BYTES>>>((const __half*)xptr, (const __half*)wptr,
                                            bias, out, mtiles);
}

// round 6
// speedup vs baseline: 6.9762x; 1.1505x over previous
#include <cuda_runtime.h>
#include <cuda_fp16.h>
#include <cstdint>

#define IN_F   4096
#define OUT_F  11008
#define M_MAX  8192
#define NGROUPS (OUT_F * (IN_F / 16))   // 2818048

// ---------------- scratch (static device arrays) ----------------
__device__ __align__(1024) __half g_wh[(size_t)OUT_F * IN_F];  // dequantized W, fp16
__device__ __align__(1024) __half g_xh[(size_t)M_MAX * IN_F];  // X, fp16

__device__ __forceinline__ uint32_t h2u(__half2 h) {
    union { __half2 h; uint32_t u; } c;
    c.h = h;
    return c.u;
}

// ---------------- kernel 1: dequant W -> fp16 ----------------
__global__ void dequant_w_kernel(const int* __restrict__ Q, const float* __restrict__ NORM) {
    size_t g = (size_t)blockIdx.x * 256 + threadIdx.x;  // exactly NGROUPS threads
    const int4* qp = reinterpret_cast<const int4*>(Q + g * 8);
    int4 q0 = qp[0];
    int4 q1 = qp[1];
    float n = NORM[g];
    float s = n * (2.0f / 7.0f);
    int v[8] = {q0.x, q0.y, q0.z, q0.w, q1.x, q1.y, q1.z, q1.w};
    uint32_t h[8];
#pragma unroll
    for (int i = 0; i < 8; i++) {
        float w0 = fmaf((float)(v[i] & 7), s, -n);
        float w1 = fmaf((float)((v[i] >> 3) & 7), s, -n);
        h[i] = h2u(__floats2half2_rn(w0, w1));
    }
    uint4* dst = reinterpret_cast<uint4*>(g_wh + g * 16);
    uint4 o0, o1;
    o0.x = h[0]; o0.y = h[1]; o0.z = h[2]; o0.w = h[3];
    o1.x = h[4]; o1.y = h[5]; o1.z = h[6]; o1.w = h[7];
    dst[0] = o0;
    dst[1] = o1;
}

// ---------------- kernel 2: X -> fp16 ----------------
__global__ void conv_x_kernel(const float4* __restrict__ X) {
    size_t i = (size_t)blockIdx.x * 256 + threadIdx.x;   // each handles 8 floats
    float4 v0 = X[2 * i];
    float4 v1 = X[2 * i + 1];
    uint4 o;
    o.x = h2u(__floats2half2_rn(v0.x, v0.y));
    o.y = h2u(__floats2half2_rn(v0.z, v0.w));
    o.z = h2u(__floats2half2_rn(v1.x, v1.y));
    o.w = h2u(__floats2half2_rn(v1.z, v1.w));
    reinterpret_cast<uint4*>(g_xh)[i] = o;
}

// ---------------- kernel 3: pipelined fp16 mma GEMM ----------------
// CTA tile 128(M) x 256(N) x 64(K halves). 8 warps in 2(M) x 4(N), each 64x64.
// Smem row = 64 halves = 128 B = 32 words, XOR-16B swizzle (verified r3/r5).
#define BM 128
#define BN 256
#define BKH 64                                   // K per tile, in halves
#define ROWW 32                                  // words per smem row
#define STAGES 3
#define A_WORDS (BM * ROWW)                      // 4096
#define B_WORDS (BN * ROWW)                      // 8192
#define STAGE_WORDS (A_WORDS + B_WORDS)          // 12288 words = 48 KB
#define SMEM_BYTES (STAGES * STAGE_WORDS * 4)    // 144 KB
#define NKT (IN_F / BKH)                          // 64

__device__ __forceinline__ void cp16(uint32_t dst, const void* src) {
    asm volatile("cp.async.cg.shared.global [%0], [%1], 16;" :: "r"(dst), "l"(src));
}

__device__ __forceinline__ void mma_f16(float* d, const uint32_t* a, const uint32_t* b) {
    asm volatile(
        "mma.sync.aligned.m16n8k16.row.col.f32.f16.f16.f32 "
        "{%0,%1,%2,%3}, {%4,%5,%6,%7}, {%8,%9}, {%0,%1,%2,%3};"
        : "+f"(d[0]), "+f"(d[1]), "+f"(d[2]), "+f"(d[3])
        : "r"(a[0]), "r"(a[1]), "r"(a[2]), "r"(a[3]),
          "r"(b[0]), "r"(b[1]));
}

__global__ __launch_bounds__(256, 1)
void gemm_mma_f16(const __half* __restrict__ A,     // g_xh [M, K]
                  const __half* __restrict__ B,     // g_wh [N, K]
                  const float* __restrict__ bias,
                  float* __restrict__ C,
                  int mtiles)
{
    extern __shared__ __align__(1024) uint32_t smw[];
    const int tid  = threadIdx.x;
    const int lane = tid & 31;
    const int warp = tid >> 5;
    const int wm   = warp & 1;          // M dir: 64 rows each
    const int wn   = warp >> 1;         // N dir: 64 cols each
    const int g    = lane >> 2;         // 0..7
    const int tig  = lane & 3;          // 0..3

    // ---- grouped rasterization (8 m-tiles per group, B L2-resident) ----
    const int NT = OUT_F / BN;          // 43
    const int GM = 8;
    int bid   = blockIdx.x;
    int grp   = bid / (GM * NT);
    int first = grp * GM;
    int gsz   = (mtiles - first < GM) ? (mtiles - first) : GM;
    int rem   = bid - grp * GM * NT;
    int mt    = first + rem % gsz;
    int nt    = rem / gsz;
    const int m0 = mt * BM;
    const int n0 = nt * BN;

    const __half* gA = A + (size_t)m0 * IN_F;
    const __half* gB = B + (size_t)n0 * IN_F;

    // loader map: row = lrow + 32*i, 16B chunk lkc (8 chunks per 128B row)
    const int lrow = tid >> 3;          // 0..31
    const int lkc  = tid & 7;
    const uint32_t s_base = (uint32_t)__cvta_generic_to_shared(smw);

    float acc[4][8][4];
#pragma unroll
    for (int mi = 0; mi < 4; mi++)
#pragma unroll
        for (int ni = 0; ni < 8; ni++)
#pragma unroll
            for (int q = 0; q < 4; q++) acc[mi][ni][q] = 0.0f;

#define LOAD_TILE(stg, kt) do {                                                   \
    uint32_t sa = s_base + (uint32_t)((stg) * STAGE_WORDS) * 4;                   \
    uint32_t sb = sa + A_WORDS * 4;                                               \
    _Pragma("unroll")                                                             \
    for (int i = 0; i < 4; i++) {                                                 \
        int row = lrow + i * 32;                                                  \
        uint32_t schunk = (uint32_t)(lkc ^ (row & 7));                            \
        cp16(sa + (uint32_t)(row * ROWW + schunk * 4) * 4,                        \
             gA + (size_t)row * IN_F + (kt) * BKH + lkc * 8);                     \
    }                                                                             \
    _Pragma("unroll")                                                             \
    for (int i = 0; i < 8; i++) {                                                 \
        int row = lrow + i * 32;                                                  \
        uint32_t schunk = (uint32_t)(lkc ^ (row & 7));                            \
        cp16(sb + (uint32_t)(row * ROWW + schunk * 4) * 4,                        \
             gB + (size_t)row * IN_F + (kt) * BKH + lkc * 8);                     \
    }                                                                             \
    asm volatile("cp.async.commit_group;");                                       \
} while (0)

#pragma unroll
    for (int s = 0; s < STAGES - 1; s++) LOAD_TILE(s, s);

    for (int t = 0; t < NKT; t++) {
        asm volatile("cp.async.wait_group %0;" :: "n"(STAGES - 2));
        __syncthreads();

        int nxt = t + STAGES - 1;
        if (nxt < NKT) {
            LOAD_TILE(nxt % STAGES, nxt);
        } else {
            asm volatile("cp.async.commit_group;");
        }

        const uint32_t* sA = smw + (t % STAGES) * STAGE_WORDS;
        const uint32_t* sB = sA + A_WORDS;
#pragma unroll
        for (int ks = 0; ks < 4; ks++) {
            const int k0w = ks * 8;                       // word base within row
            const int ca0 = (k0w + tig) ^ (g << 2);
            const int ca1 = ca0 ^ 4;

            uint32_t a[4][4], b[8][2];
#pragma unroll
            for (int mi = 0; mi < 4; mi++) {
                const uint32_t* ar = sA + (wm * 64 + mi * 16 + g) * ROWW;
                a[mi][0] = ar[ca0];
                a[mi][1] = ar[8 * ROWW + ca0];
                a[mi][2] = ar[ca1];
                a[mi][3] = ar[8 * ROWW + ca1];
            }
#pragma unroll
            for (int ni = 0; ni < 8; ni++) {
                const uint32_t* br = sB + (wn * 64 + ni * 8 + g) * ROWW;
                b[ni][0] = br[ca0];
                b[ni][1] = br[ca1];
            }
#pragma unroll
            for (int mi = 0; mi < 4; mi++)
#pragma unroll
                for (int ni = 0; ni < 8; ni++)
                    mma_f16(acc[mi][ni], a[mi], b[ni]);
        }
        __syncthreads();
    }

    // ---- epilogue: bias + store ----
#pragma unroll
    for (int mi = 0; mi < 4; mi++) {
        const int row = m0 + wm * 64 + mi * 16 + g;
        float* c0 = C + (size_t)row * OUT_F;
        float* c1 = C + (size_t)(row + 8) * OUT_F;
#pragma unroll
        for (int ni = 0; ni < 8; ni++) {
            const int col = n0 + wn * 64 + ni * 8 + tig * 2;
            float2 bv = *reinterpret_cast<const float2*>(bias + col);
            float2 o0, o1;
            o0.x = acc[mi][ni][0] + bv.x;
            o0.y = acc[mi][ni][1] + bv.y;
            o1.x = acc[mi][ni][2] + bv.x;
            o1.y = acc[mi][ni][3] + bv.y;
            *reinterpret_cast<float2*>(c0 + col) = o0;
            *reinterpret_cast<float2*>(c1 + col) = o1;
        }
    }
}

// ---------------- host launcher ----------------
extern "C" void kernel_launch(void* const* d_in, const int* in_sizes, int n_in,
                              void* d_out, int out_size)
{
    const float* x    = (const float*)d_in[0];
    const int*   q3   = (const int*)  d_in[1];
    const float* nrm  = (const float*)d_in[2];
    const float* bias = (const float*)d_in[3];
    float* out = (float*)d_out;

    const int M = in_sizes[0] / IN_F;            // 8192

    void* wptr = nullptr; cudaGetSymbolAddress(&wptr, g_wh);
    void* xptr = nullptr; cudaGetSymbolAddress(&xptr, g_xh);

    dequant_w_kernel<<<NGROUPS / 256, 256>>>(q3, nrm);
    conv_x_kernel<<<(int)(((size_t)M * IN_F / 8) / 256), 256>>>(
        reinterpret_cast<const float4*>(x));

    cudaFuncSetAttribute(gemm_mma_f16,
                         cudaFuncAttributeMaxDynamicSharedMemorySize, SMEM_BYTES);
    const int mtiles = M / BM;                   // 64
    const int grid = mtiles * (OUT_F / BN);      // 64 * 43 = 2752
    gemm_mma_f16<<<grid, 256, SMEM_BYTES>>>((const __half*)xptr, (const __half*)wptr,
                                            bias, out, mtiles);
}

// round 7
// speedup vs baseline: 7.0945x; 1.0169x over previous
#include <cuda_runtime.h>
#include <cuda_fp16.h>
#include <cstdint>

#define IN_F   4096
#define OUT_F  11008
#define M_MAX  8192
#define NGROUPS (OUT_F * (IN_F / 16))   // 2818048

// ---------------- scratch (static device arrays) ----------------
__device__ __align__(1024) __half g_wh[(size_t)OUT_F * IN_F];  // dequantized W, fp16
__device__ __align__(1024) __half g_xh[(size_t)M_MAX * IN_F];  // X, fp16

__device__ __forceinline__ uint32_t h2u(__half2 h) {
    union { __half2 h; uint32_t u; } c;
    c.h = h;
    return c.u;
}

// ---------------- kernel 1: dequant W -> fp16 ----------------
__global__ void dequant_w_kernel(const int* __restrict__ Q, const float* __restrict__ NORM) {
    size_t g = (size_t)blockIdx.x * 256 + threadIdx.x;  // exactly NGROUPS threads
    const int4* qp = reinterpret_cast<const int4*>(Q + g * 8);
    int4 q0 = qp[0];
    int4 q1 = qp[1];
    float n = NORM[g];
    float s = n * (2.0f / 7.0f);
    int v[8] = {q0.x, q0.y, q0.z, q0.w, q1.x, q1.y, q1.z, q1.w};
    uint32_t h[8];
#pragma unroll
    for (int i = 0; i < 8; i++) {
        float w0 = fmaf((float)(v[i] & 7), s, -n);
        float w1 = fmaf((float)((v[i] >> 3) & 7), s, -n);
        h[i] = h2u(__floats2half2_rn(w0, w1));
    }
    uint4* dst = reinterpret_cast<uint4*>(g_wh + g * 16);
    uint4 o0, o1;
    o0.x = h[0]; o0.y = h[1]; o0.z = h[2]; o0.w = h[3];
    o1.x = h[4]; o1.y = h[5]; o1.z = h[6]; o1.w = h[7];
    dst[0] = o0;
    dst[1] = o1;
}

// ---------------- kernel 2: X -> fp16 ----------------
__global__ void conv_x_kernel(const float4* __restrict__ X) {
    size_t i = (size_t)blockIdx.x * 256 + threadIdx.x;   // each handles 8 floats
    float4 v0 = X[2 * i];
    float4 v1 = X[2 * i + 1];
    uint4 o;
    o.x = h2u(__floats2half2_rn(v0.x, v0.y));
    o.y = h2u(__floats2half2_rn(v0.z, v0.w));
    o.z = h2u(__floats2half2_rn(v1.x, v1.y));
    o.w = h2u(__floats2half2_rn(v1.z, v1.w));
    reinterpret_cast<uint4*>(g_xh)[i] = o;
}

// ---------------- kernel 3: pipelined fp16 mma GEMM (ldmatrix) ----------------
// CTA tile 128(M) x 256(N) x 64(K halves). 8 warps in 2(M) x 4(N), each 64x64.
// Smem row = 64 halves = 128 B, XOR-16B-chunk swizzle (same as r3/r5/r6).
#define BM 128
#define BN 256
#define BKH 64
#define ROWW 32                                  // words per smem row
#define STAGES 3
#define A_WORDS (BM * ROWW)                      // 4096
#define B_WORDS (BN * ROWW)                      // 8192
#define STAGE_WORDS (A_WORDS + B_WORDS)          // 12288 words = 48 KB
#define SMEM_BYTES (STAGES * STAGE_WORDS * 4)    // 144 KB
#define NKT (IN_F / BKH)                          // 64

__device__ __forceinline__ void cp16(uint32_t dst, const void* src) {
    asm volatile("cp.async.cg.shared.global [%0], [%1], 16;" :: "r"(dst), "l"(src));
}

__device__ __forceinline__ void ldsm4(uint32_t* r, uint32_t addr) {
    asm volatile("ldmatrix.sync.aligned.m8n8.x4.shared.b16 {%0,%1,%2,%3}, [%4];"
        : "=r"(r[0]), "=r"(r[1]), "=r"(r[2]), "=r"(r[3]) : "r"(addr));
}

__device__ __forceinline__ void mma_f16(float* d, const uint32_t* a, const uint32_t* b) {
    asm volatile(
        "mma.sync.aligned.m16n8k16.row.col.f32.f16.f16.f32 "
        "{%0,%1,%2,%3}, {%4,%5,%6,%7}, {%8,%9}, {%0,%1,%2,%3};"
        : "+f"(d[0]), "+f"(d[1]), "+f"(d[2]), "+f"(d[3])
        : "r"(a[0]), "r"(a[1]), "r"(a[2]), "r"(a[3]),
          "r"(b[0]), "r"(b[1]));
}

__global__ __launch_bounds__(256, 1)
void gemm_mma_f16(const __half* __restrict__ A,     // g_xh [M, K]
                  const __half* __restrict__ B,     // g_wh [N, K]
                  const float* __restrict__ bias,
                  float* __restrict__ C,
                  int mtiles)
{
    extern __shared__ __align__(1024) uint32_t smw[];
    const int tid  = threadIdx.x;
    const int lane = tid & 31;
    const int warp = tid >> 5;
    const int wm   = warp & 1;          // M dir: 64 rows each
    const int wn   = warp >> 1;         // N dir: 64 cols each
    const int g    = lane >> 2;         // 0..7
    const int tig  = lane & 3;          // 0..3

    // ---- grouped rasterization ----
    const int NT = OUT_F / BN;          // 43
    const int GM = 8;
    int bid   = blockIdx.x;
    int grp   = bid / (GM * NT);
    int first = grp * GM;
    int gsz   = (mtiles - first < GM) ? (mtiles - first) : GM;
    int rem   = bid - grp * GM * NT;
    int mt    = first + rem % gsz;
    int nt    = rem / gsz;
    const int m0 = mt * BM;
    const int n0 = nt * BN;

    const __half* gA = A + (size_t)m0 * IN_F;
    const __half* gB = B + (size_t)n0 * IN_F;

    // loader map
    const int lrow = tid >> 3;          // 0..31
    const int lkc  = tid & 7;
    const uint32_t s_base = (uint32_t)__cvta_generic_to_shared(smw);

    // ---- ldmatrix per-lane address components ----
    const int p  = lane >> 3;           // matrix part 0..3
    const int rl = lane & 7;            // row within 8-row matrix
    // A: m0/m1 = chunk lo rows +0/+8 ; m2/m3 = chunk hi rows +0/+8
    const int a_cbit = p >> 1;
    const int a_roff = rl + (p & 1) * 8;
    // B: m0/m1 = rows +0 chunks lo/hi ; m2/m3 = rows +8 chunks lo/hi
    const int b_cbit = p & 1;
    const int b_roff = rl + (p >> 1) * 8;

    uint32_t a_rowb[4], b_rowb[4];      // byte offsets of row bases
#pragma unroll
    for (int mi = 0; mi < 4; mi++) a_rowb[mi] = (uint32_t)(wm * 64 + mi * 16 + a_roff) * 128;
#pragma unroll
    for (int nj = 0; nj < 4; nj++) b_rowb[nj] = (uint32_t)(wn * 64 + nj * 16 + b_roff) * 128;

    float acc[4][8][4];
#pragma unroll
    for (int mi = 0; mi < 4; mi++)
#pragma unroll
        for (int ni = 0; ni < 8; ni++)
#pragma unroll
            for (int q = 0; q < 4; q++) acc[mi][ni][q] = 0.0f;

#define LOAD_TILE(stg, kt) do {                                                   \
    uint32_t sa = s_base + (uint32_t)((stg) * STAGE_WORDS) * 4;                   \
    uint32_t sb = sa + A_WORDS * 4;                                               \
    _Pragma("unroll")                                                             \
    for (int i = 0; i < 4; i++) {                                                 \
        int row = lrow + i * 32;                                                  \
        uint32_t schunk = (uint32_t)(lkc ^ (row & 7));                            \
        cp16(sa + (uint32_t)(row * ROWW + schunk * 4) * 4,                        \
             gA + (size_t)row * IN_F + (kt) * BKH + lkc * 8);                     \
    }                                                                             \
    _Pragma("unroll")                                                             \
    for (int i = 0; i < 8; i++) {                                                 \
        int row = lrow + i * 32;                                                  \
        uint32_t schunk = (uint32_t)(lkc ^ (row & 7));                            \
        cp16(sb + (uint32_t)(row * ROWW + schunk * 4) * 4,                        \
             gB + (size_t)row * IN_F + (kt) * BKH + lkc * 8);                     \
    }                                                                             \
    asm volatile("cp.async.commit_group;");                                       \
} while (0)

    // frag load for k-step ks from stage bases (byte addrs)
#define LD_FRAGS(buf, ks, sAb, sBb) do {                                          \
    uint32_t asw = (uint32_t)(((2 * (ks) + a_cbit) ^ rl) << 4);                   \
    uint32_t bsw = (uint32_t)(((2 * (ks) + b_cbit) ^ rl) << 4);                   \
    _Pragma("unroll")                                                             \
    for (int mi = 0; mi < 4; mi++) ldsm4(af[buf][mi], (sAb) + a_rowb[mi] + asw);  \
    _Pragma("unroll")                                                             \
    for (int nj = 0; nj < 4; nj++) ldsm4(bf[buf][nj], (sBb) + b_rowb[nj] + bsw);  \
} while (0)

    uint32_t af[2][4][4], bf[2][4][4];

#pragma unroll
    for (int s = 0; s < STAGES - 1; s++) LOAD_TILE(s, s);

    for (int t = 0; t < NKT; t++) {
        asm volatile("cp.async.wait_group %0;" :: "n"(STAGES - 2));
        __syncthreads();

        const uint32_t sAb = s_base + (uint32_t)((t % STAGES) * STAGE_WORDS) * 4;
        const uint32_t sBb = sAb + A_WORDS * 4;

        // fragments for ks=0 first (gets MMAs started), then issue next tile loads
        LD_FRAGS(0, 0, sAb, sBb);

        int nxt = t + STAGES - 1;
        if (nxt < NKT) {
            LOAD_TILE(nxt % STAGES, nxt);
        } else {
            asm volatile("cp.async.commit_group;");
        }

#pragma unroll
        for (int ks = 0; ks < 4; ks++) {
            const int cur = ks & 1;
            if (ks < 3) LD_FRAGS(cur ^ 1, ks + 1, sAb, sBb);
#pragma unroll
            for (int mi = 0; mi < 4; mi++)
#pragma unroll
                for (int ni = 0; ni < 8; ni++)
                    mma_f16(acc[mi][ni], af[cur][mi], &bf[cur][ni >> 1][(ni & 1) * 2]);
        }
        __syncthreads();
    }

    // ---- epilogue: bias + store ----
#pragma unroll
    for (int mi = 0; mi < 4; mi++) {
        const int row = m0 + wm * 64 + mi * 16 + g;
        float* c0 = C + (size_t)row * OUT_F;
        float* c1 = C + (size_t)(row + 8) * OUT_F;
#pragma unroll
        for (int ni = 0; ni < 8; ni++) {
            const int col = n0 + wn * 64 + ni * 8 + tig * 2;
            float2 bv = *reinterpret_cast<const float2*>(bias + col);
            float2 o0, o1;
            o0.x = acc[mi][ni][0] + bv.x;
            o0.y = acc[mi][ni][1] + bv.y;
            o1.x = acc[mi][ni][2] + bv.x;
            o1.y = acc[mi][ni][3] + bv.y;
            *reinterpret_cast<float2*>(c0 + col) = o0;
            *reinterpret_cast<float2*>(c1 + col) = o1;
        }
    }
}

// ---------------- host launcher ----------------
extern "C" void kernel_launch(void* const* d_in, const int* in_sizes, int n_in,
                              void* d_out, int out_size)
{
    const float* x    = (const float*)d_in[0];
    const int*   q3   = (const int*)  d_in[1];
    const float* nrm  = (const float*)d_in[2];
    const float* bias = (const float*)d_in[3];
    float* out = (float*)d_out;

    const int M = in_sizes[0] / IN_F;            // 8192

    void* wptr = nullptr; cudaGetSymbolAddress(&wptr, g_wh);
    void* xptr = nullptr; cudaGetSymbolAddress(&xptr, g_xh);

    dequant_w_kernel<<<NGROUPS / 256, 256>>>(q3, nrm);
    conv_x_kernel<<<(int)(((size_t)M * IN_F / 8) / 256), 256>>>(
        reinterpret_cast<const float4*>(x));

    cudaFuncSetAttribute(gemm_mma_f16,
                         cudaFuncAttributeMaxDynamicSharedMemorySize, SMEM_BYTES);
    const int mtiles = M / BM;                   // 64
    const int grid = mtiles * (OUT_F / BN);      // 64 * 43 = 2752
    gemm_mma_f16<<<grid, 256, SMEM_BYTES>>>((const __half*)xptr, (const __half*)wptr,
                                            bias, out, mtiles);
}

// round 8
// speedup vs baseline: 7.4227x; 1.0463x over previous
#include <cuda_runtime.h>
#include <cuda_fp16.h>
#include <cstdint>

#define IN_F   4096
#define OUT_F  11008
#define M_MAX  8192
#define NGROUPS (OUT_F * (IN_F / 16))   // 2818048

// ---------------- scratch (static device arrays) ----------------
__device__ __align__(1024) __half g_wh[(size_t)OUT_F * IN_F];  // dequantized W, fp16
__device__ __align__(1024) __half g_xh[(size_t)M_MAX * IN_F];  // X, fp16

__device__ __forceinline__ uint32_t h2u(__half2 h) {
    union { __half2 h; uint32_t u; } c;
    c.h = h;
    return c.u;
}

// ---------------- kernel 1: dequant W -> fp16 ----------------
__global__ void dequant_w_kernel(const int* __restrict__ Q, const float* __restrict__ NORM) {
    size_t g = (size_t)blockIdx.x * 256 + threadIdx.x;  // exactly NGROUPS threads
    const int4* qp = reinterpret_cast<const int4*>(Q + g * 8);
    int4 q0 = qp[0];
    int4 q1 = qp[1];
    float n = NORM[g];
    float s = n * (2.0f / 7.0f);
    int v[8] = {q0.x, q0.y, q0.z, q0.w, q1.x, q1.y, q1.z, q1.w};
    uint32_t h[8];
#pragma unroll
    for (int i = 0; i < 8; i++) {
        float w0 = fmaf((float)(v[i] & 7), s, -n);
        float w1 = fmaf((float)((v[i] >> 3) & 7), s, -n);
        h[i] = h2u(__floats2half2_rn(w0, w1));
    }
    uint4* dst = reinterpret_cast<uint4*>(g_wh + g * 16);
    uint4 o0, o1;
    o0.x = h[0]; o0.y = h[1]; o0.z = h[2]; o0.w = h[3];
    o1.x = h[4]; o1.y = h[5]; o1.z = h[6]; o1.w = h[7];
    dst[0] = o0;
    dst[1] = o1;
}

// ---------------- kernel 2: X -> fp16 ----------------
__global__ void conv_x_kernel(const float4* __restrict__ X) {
    size_t i = (size_t)blockIdx.x * 256 + threadIdx.x;   // each handles 8 floats
    float4 v0 = X[2 * i];
    float4 v1 = X[2 * i + 1];
    uint4 o;
    o.x = h2u(__floats2half2_rn(v0.x, v0.y));
    o.y = h2u(__floats2half2_rn(v0.z, v0.w));
    o.z = h2u(__floats2half2_rn(v1.x, v1.y));
    o.w = h2u(__floats2half2_rn(v1.z, v1.w));
    reinterpret_cast<uint4*>(g_xh)[i] = o;
}

// ---------------- kernel 3: pipelined fp16 mma GEMM ----------------
// CTA tile 128(M) x 256(N) x 64(K halves), 512 threads = 16 warps in 4(M) x 4(N),
// warp tile 32 x 64. 4 stages, ONE __syncthreads per k-iter.
// Smem row = 64 halves = 128 B, XOR-16B-chunk swizzle (verified r3..r7).
#define BM 128
#define BN 256
#define BKH 64
#define ROWW 32                                  // words per smem row
#define STAGES 4
#define A_WORDS (BM * ROWW)                      // 4096
#define B_WORDS (BN * ROWW)                      // 8192
#define STAGE_WORDS (A_WORDS + B_WORDS)          // 12288 words = 48 KB
#define SMEM_BYTES (STAGES * STAGE_WORDS * 4)    // 192 KB
#define NKT (IN_F / BKH)                          // 64
#define NTH 512

__device__ __forceinline__ void cp16(uint32_t dst, const void* src) {
    asm volatile("cp.async.cg.shared.global [%0], [%1], 16;" :: "r"(dst), "l"(src));
}

__device__ __forceinline__ void ldsm4(uint32_t* r, uint32_t addr) {
    asm volatile("ldmatrix.sync.aligned.m8n8.x4.shared.b16 {%0,%1,%2,%3}, [%4];"
        : "=r"(r[0]), "=r"(r[1]), "=r"(r[2]), "=r"(r[3]) : "r"(addr));
}

__device__ __forceinline__ void mma_f16(float* d, const uint32_t* a, const uint32_t* b) {
    asm volatile(
        "mma.sync.aligned.m16n8k16.row.col.f32.f16.f16.f32 "
        "{%0,%1,%2,%3}, {%4,%5,%6,%7}, {%8,%9}, {%0,%1,%2,%3};"
        : "+f"(d[0]), "+f"(d[1]), "+f"(d[2]), "+f"(d[3])
        : "r"(a[0]), "r"(a[1]), "r"(a[2]), "r"(a[3]),
          "r"(b[0]), "r"(b[1]));
}

__global__ __launch_bounds__(NTH, 1)
void gemm_mma_f16(const __half* __restrict__ A,     // g_xh [M, K]
                  const __half* __restrict__ B,     // g_wh [N, K]
                  const float* __restrict__ bias,
                  float* __restrict__ C,
                  int mtiles)
{
    extern __shared__ __align__(1024) uint32_t smw[];
    const int tid  = threadIdx.x;
    const int lane = tid & 31;
    const int warp = tid >> 5;
    const int wm   = warp & 3;          // M dir: 32 rows each
    const int wn   = warp >> 2;         // N dir: 64 cols each

    // ---- grouped rasterization ----
    const int NT = OUT_F / BN;          // 43
    const int GM = 8;
    int bid   = blockIdx.x;
    int grp   = bid / (GM * NT);
    int first = grp * GM;
    int gsz   = (mtiles - first < GM) ? (mtiles - first) : GM;
    int rem   = bid - grp * GM * NT;
    int mt    = first + rem % gsz;
    int nt    = rem / gsz;
    const int m0 = mt * BM;
    const int n0 = nt * BN;

    const __half* gA = A + (size_t)m0 * IN_F;
    const __half* gB = B + (size_t)n0 * IN_F;

    // loader map: 512 threads; A: 2 rows each (stride 64), B: 4 rows each
    const int lrow = tid >> 3;          // 0..63
    const int lkc  = tid & 7;
    const uint32_t s_base = (uint32_t)__cvta_generic_to_shared(smw);

    // ---- ldmatrix per-lane address components (same derivation as r7) ----
    const int p  = lane >> 3;           // matrix part 0..3
    const int rl = lane & 7;            // row within 8-row matrix
    const int a_cbit = p >> 1;
    const int a_roff = rl + (p & 1) * 8;
    const int b_cbit = p & 1;
    const int b_roff = rl + (p >> 1) * 8;

    uint32_t a_rowb[2], b_rowb[4];      // byte offsets of row bases
#pragma unroll
    for (int mi = 0; mi < 2; mi++) a_rowb[mi] = (uint32_t)(wm * 32 + mi * 16 + a_roff) * 128;
#pragma unroll
    for (int nj = 0; nj < 4; nj++) b_rowb[nj] = (uint32_t)(wn * 64 + nj * 16 + b_roff) * 128;

    float acc[2][8][4];
#pragma unroll
    for (int mi = 0; mi < 2; mi++)
#pragma unroll
        for (int ni = 0; ni < 8; ni++)
#pragma unroll
            for (int q = 0; q < 4; q++) acc[mi][ni][q] = 0.0f;

#define LOAD_TILE(stg, kt) do {                                                   \
    uint32_t sa = s_base + (uint32_t)((stg) * STAGE_WORDS) * 4;                   \
    uint32_t sb = sa + A_WORDS * 4;                                               \
    _Pragma("unroll")                                                             \
    for (int i = 0; i < 2; i++) {                                                 \
        int row = lrow + i * 64;                                                  \
        uint32_t schunk = (uint32_t)(lkc ^ (row & 7));                            \
        cp16(sa + (uint32_t)(row * ROWW + schunk * 4) * 4,                        \
             gA + (size_t)row * IN_F + (kt) * BKH + lkc * 8);                     \
    }                                                                             \
    _Pragma("unroll")                                                             \
    for (int i = 0; i < 4; i++) {                                                 \
        int row = lrow + i * 64;                                                  \
        uint32_t schunk = (uint32_t)(lkc ^ (row & 7));                            \
        cp16(sb + (uint32_t)(row * ROWW + schunk * 4) * 4,                        \
             gB + (size_t)row * IN_F + (kt) * BKH + lkc * 8);                     \
    }                                                                             \
    asm volatile("cp.async.commit_group;");                                       \
} while (0)

    uint32_t af[2][4], bf[4][4];

#define LD_FRAGS(ks, sAb, sBb) do {                                               \
    uint32_t asw = (uint32_t)(((2 * (ks) + a_cbit) ^ rl) << 4);                   \
    uint32_t bsw = (uint32_t)(((2 * (ks) + b_cbit) ^ rl) << 4);                   \
    _Pragma("unroll")                                                             \
    for (int mi = 0; mi < 2; mi++) ldsm4(af[mi], (sAb) + a_rowb[mi] + asw);       \
    _Pragma("unroll")                                                             \
    for (int nj = 0; nj < 4; nj++) ldsm4(bf[nj], (sBb) + b_rowb[nj] + bsw);       \
} while (0)

    // prologue: stages 0..2
#pragma unroll
    for (int s = 0; s < STAGES - 1; s++) LOAD_TILE(s, s);

    for (int t = 0; t < NKT; t++) {
        asm volatile("cp.async.wait_group %0;" :: "n"(STAGES - 2));
        __syncthreads();   // single barrier per iter (4-stage WAR slack)

        const uint32_t sAb = s_base + (uint32_t)((t % STAGES) * STAGE_WORDS) * 4;
        const uint32_t sBb = sAb + A_WORDS * 4;

        int nxt = t + STAGES - 1;
        if (nxt < NKT) {
            LOAD_TILE(nxt % STAGES, nxt);
        } else {
            asm volatile("cp.async.commit_group;");
        }

#pragma unroll
        for (int ks = 0; ks < 4; ks++) {
            LD_FRAGS(ks, sAb, sBb);
#pragma unroll
            for (int mi = 0; mi < 2; mi++)
#pragma unroll
                for (int ni = 0; ni < 8; ni++)
                    mma_f16(acc[mi][ni], af[mi], &bf[ni >> 1][(ni & 1) * 2]);
        }
    }

    // ---- epilogue: bias + store ----
    const int g = lane >> 2;
    const int tig = lane & 3;
#pragma unroll
    for (int mi = 0; mi < 2; mi++) {
        const int row = m0 + wm * 32 + mi * 16 + g;
        float* c0 = C + (size_t)row * OUT_F;
        float* c1 = C + (size_t)(row + 8) * OUT_F;
#pragma unroll
        for (int ni = 0; ni < 8; ni++) {
            const int col = n0 + wn * 64 + ni * 8 + tig * 2;
            float2 bv = *reinterpret_cast<const float2*>(bias + col);
            float2 o0, o1;
            o0.x = acc[mi][ni][0] + bv.x;
            o0.y = acc[mi][ni][1] + bv.y;
            o1.x = acc[mi][ni][2] + bv.x;
            o1.y = acc[mi][ni][3] + bv.y;
            *reinterpret_cast<float2*>(c0 + col) = o0;
            *reinterpret_cast<float2*>(c1 + col) = o1;
        }
    }
}

// ---------------- host launcher ----------------
extern "C" void kernel_launch(void* const* d_in, const int* in_sizes, int n_in,
                              void* d_out, int out_size)
{
    const float* x    = (const float*)d_in[0];
    const int*   q3   = (const int*)  d_in[1];
    const float* nrm  = (const float*)d_in[2];
    const float* bias = (const float*)d_in[3];
    float* out = (float*)d_out;

    const int M = in_sizes[0] / IN_F;            // 8192

    void* wptr = nullptr; cudaGetSymbolAddress(&wptr, g_wh);
    void* xptr = nullptr; cudaGetSymbolAddress(&xptr, g_xh);

    dequant_w_kernel<<<NGROUPS / 256, 256>>>(q3, nrm);
    conv_x_kernel<<<(int)(((size_t)M * IN_F / 8) / 256), 256>>>(
        reinterpret_cast<const float4*>(x));

    cudaFuncSetAttribute(gemm_mma_f16,
                         cudaFuncAttributeMaxDynamicSharedMemorySize, SMEM_BYTES);
    const int mtiles = M / BM;                   // 64
    const int grid = mtiles * (OUT_F / BN);      // 64 * 43 = 2752
    gemm_mma_f16<<<grid, NTH, SMEM_BYTES>>>((const __half*)xptr, (const __half*)wptr,
                                            bias, out, mtiles);
}